// round 1
// baseline (speedup 1.0000x reference)
#include <cuda_runtime.h>

#define BATCH 4
#define TSEQ  2048
#define CDIM  1024
#define NHEAD 16
#define HSZ   64
#define FDIM  4096
#define BT    (BATCH * TSEQ)   // 8192
#define LN_EPS 1e-5f

// ---------------- scratch (device globals: allocation-free) ----------------
__device__ float g_h1[BT * CDIM];    // ln1 output
__device__ float g_q [BT * CDIM];    // [B,H,T,HS]
__device__ float g_k [BT * CDIM];
__device__ float g_v [BT * CDIM];
__device__ float g_att[BT * CDIM];   // attention out, [B,T,C]
__device__ float g_x2[BT * CDIM];    // x + att@Wo + bo
__device__ float g_h2[BT * CDIM];    // ln2 output
__device__ float g_ff[BT * FDIM];    // relu(h2@W1+b1)

// ---------------- LayerNorm over TIME axis (axis=1), ddof=1 ----------------
// grid (BATCH, CDIM/32), block (32, 16). Thread x = channel (coalesced), y = t-slice.
__global__ void ln_time_kernel(const float* __restrict__ x,
                               const float* __restrict__ gamma,
                               const float* __restrict__ beta,
                               float* __restrict__ out) {
    int b  = blockIdx.x;
    int c  = blockIdx.y * 32 + threadIdx.x;
    int ty = threadIdx.y;
    const float* xp = x + (size_t)b * TSEQ * CDIM + c;

    float s = 0.f, s2 = 0.f;
    for (int t = ty; t < TSEQ; t += 16) {
        float v = xp[(size_t)t * CDIM];
        s += v; s2 += v * v;
    }
    __shared__ float sh1[16][33];
    __shared__ float sh2[16][33];
    sh1[ty][threadIdx.x] = s;
    sh2[ty][threadIdx.x] = s2;
    __syncthreads();
    for (int off = 8; off; off >>= 1) {
        if (ty < off) {
            sh1[ty][threadIdx.x] += sh1[ty + off][threadIdx.x];
            sh2[ty][threadIdx.x] += sh2[ty + off][threadIdx.x];
        }
        __syncthreads();
    }
    float mean = sh1[0][threadIdx.x] * (1.f / TSEQ);
    float var  = (sh2[0][threadIdx.x] - (float)TSEQ * mean * mean) * (1.f / (TSEQ - 1));
    float inv  = rsqrtf(var + LN_EPS);
    float gg = gamma[c], bb = beta[c];

    float* op = out + (size_t)b * TSEQ * CDIM + c;
    for (int t = ty; t < TSEQ; t += 16) {
        op[(size_t)t * CDIM] = (xp[(size_t)t * CDIM] - mean) * inv * gg + bb;
    }
}

// ---------------- tiled SGEMM, 128x128x8, 256 threads, 8x8/thread ----------
// MODE 0: B = [H, C, HS] stacked-head weights; out -> [B,H,T,HS] + bias
// MODE 1: out = A@B + bias + res   (row-major [M,N])
// MODE 2: out = relu(A@B + bias)
// MODE 3: out = A@B + bias + res
template <int MODE>
__global__ __launch_bounds__(256)
void gemm_kernel(const float* __restrict__ A, const float* __restrict__ Bw,
                 const float* __restrict__ bias, const float* __restrict__ res,
                 float* __restrict__ out, int M, int N, int K) {
    __shared__ float As[8][128];
    __shared__ float Bs[8][132];

    int tid = threadIdx.x;
    int m0 = blockIdx.y * 128, n0 = blockIdx.x * 128;
    int arow = tid >> 1, acol = (tid & 1) * 4;
    int brow = tid >> 5, bcol = (tid & 31) * 4;
    int tx = tid & 15, ty = tid >> 4;

    const float* Ap = A + (size_t)(m0 + arow) * K + acol;
    const float* Bp;
    if (MODE == 0) {
        int n = n0 + bcol;
        Bp = Bw + (size_t)(n >> 6) * K * 64 + (size_t)brow * 64 + (n & 63);
    } else {
        Bp = Bw + (size_t)brow * N + n0 + bcol;
    }

    float acc[8][8];
#pragma unroll
    for (int i = 0; i < 8; i++)
#pragma unroll
        for (int j = 0; j < 8; j++) acc[i][j] = 0.f;

    for (int k0 = 0; k0 < K; k0 += 8) {
        float4 a = *(const float4*)(Ap + k0);
        As[acol + 0][arow] = a.x;
        As[acol + 1][arow] = a.y;
        As[acol + 2][arow] = a.z;
        As[acol + 3][arow] = a.w;
        float4 bv;
        if (MODE == 0) bv = *(const float4*)(Bp + (size_t)k0 * 64);
        else           bv = *(const float4*)(Bp + (size_t)k0 * N);
        *(float4*)&Bs[brow][bcol] = bv;
        __syncthreads();
#pragma unroll
        for (int k = 0; k < 8; k++) {
            float ar[8], br[8];
            *(float4*)&ar[0] = *(const float4*)&As[k][ty * 8];
            *(float4*)&ar[4] = *(const float4*)&As[k][ty * 8 + 4];
            *(float4*)&br[0] = *(const float4*)&Bs[k][tx * 8];
            *(float4*)&br[4] = *(const float4*)&Bs[k][tx * 8 + 4];
#pragma unroll
            for (int i = 0; i < 8; i++)
#pragma unroll
                for (int j = 0; j < 8; j++)
                    acc[i][j] = fmaf(ar[i], br[j], acc[i][j]);
        }
        __syncthreads();
    }

#pragma unroll
    for (int i = 0; i < 8; i++) {
        int r = m0 + ty * 8 + i;
#pragma unroll
        for (int j = 0; j < 8; j++) {
            int c = n0 + tx * 8 + j;
            float v = acc[i][j] + bias[c];
            if (MODE == 0) {
                int b = r >> 11, t = r & 2047;
                int h = c >> 6, d = c & 63;
                out[((size_t)(b * NHEAD + h) * TSEQ + t) * HSZ + d] = v;
            } else if (MODE == 2) {
                out[(size_t)r * N + c] = fmaxf(v, 0.f);
            } else {
                out[(size_t)r * N + c] = v + res[(size_t)r * N + c];
            }
        }
    }
}

// ---------------- causal flash attention, BM=32, BN=64, HS=64 --------------
// grid (T/32, B*H), 256 threads. Thread (tx=tid&15, ty=tid>>4):
// owns S rows ty*2..+1, cols tx*4..+3. Row reductions via shfl within 16 lanes.
__global__ __launch_bounds__(256)
void attn_kernel(const float* __restrict__ Q, const float* __restrict__ Kg,
                 const float* __restrict__ V, float* __restrict__ Out) {
    __shared__ float Qs[32][65];
    __shared__ float Ks[64][65];   // reused to hold P after S-compute
    __shared__ float Vs[64][64];

    int bh = blockIdx.y;
    int m0 = blockIdx.x * 32;
    int tid = threadIdx.x;
    int tx = tid & 15, ty = tid >> 4;

    const float* Qb = Q  + (size_t)bh * TSEQ * HSZ;
    const float* Kb = Kg + (size_t)bh * TSEQ * HSZ;
    const float* Vb = V  + (size_t)bh * TSEQ * HSZ;

    // load Q tile (32x64)
    for (int i = tid; i < 32 * 16; i += 256) {
        int r = i >> 4, c4 = (i & 15) << 2;
        float4 qv = *(const float4*)(Qb + (size_t)(m0 + r) * HSZ + c4);
        Qs[r][c4] = qv.x; Qs[r][c4 + 1] = qv.y;
        Qs[r][c4 + 2] = qv.z; Qs[r][c4 + 3] = qv.w;
    }

    float m_i[2] = {-1e30f, -1e30f};
    float l_i[2] = {0.f, 0.f};
    float o[2][4] = {{0.f, 0.f, 0.f, 0.f}, {0.f, 0.f, 0.f, 0.f}};
    int jmax = m0 >> 6;
    __syncthreads();

    for (int j = 0; j <= jmax; j++) {
        int s0 = j << 6;
        // load K, V tiles (64x64 each)
        for (int i = tid; i < 64 * 16; i += 256) {
            int r = i >> 4, c4 = (i & 15) << 2;
            float4 kv = *(const float4*)(Kb + (size_t)(s0 + r) * HSZ + c4);
            Ks[r][c4] = kv.x; Ks[r][c4 + 1] = kv.y;
            Ks[r][c4 + 2] = kv.z; Ks[r][c4 + 3] = kv.w;
            float4 vv = *(const float4*)(Vb + (size_t)(s0 + r) * HSZ + c4);
            *(float4*)&Vs[r][c4] = vv;
        }
        __syncthreads();

        // S = Q @ K^T (2x4 per thread)
        float sacc[2][4] = {{0.f, 0.f, 0.f, 0.f}, {0.f, 0.f, 0.f, 0.f}};
#pragma unroll 8
        for (int k = 0; k < 64; k++) {
            float q0 = Qs[ty * 2][k], q1 = Qs[ty * 2 + 1][k];
            float b0 = Ks[tx * 4 + 0][k];
            float b1 = Ks[tx * 4 + 1][k];
            float b2 = Ks[tx * 4 + 2][k];
            float b3 = Ks[tx * 4 + 3][k];
            sacc[0][0] = fmaf(q0, b0, sacc[0][0]);
            sacc[0][1] = fmaf(q0, b1, sacc[0][1]);
            sacc[0][2] = fmaf(q0, b2, sacc[0][2]);
            sacc[0][3] = fmaf(q0, b3, sacc[0][3]);
            sacc[1][0] = fmaf(q1, b0, sacc[1][0]);
            sacc[1][1] = fmaf(q1, b1, sacc[1][1]);
            sacc[1][2] = fmaf(q1, b2, sacc[1][2]);
            sacc[1][3] = fmaf(q1, b3, sacc[1][3]);
        }
        __syncthreads();  // done reading Ks before P overwrites it

        // scale + causal mask (diagonal tile only)
        bool diag = (j == jmax);
#pragma unroll
        for (int i = 0; i < 2; i++) {
            int rg = m0 + ty * 2 + i;
#pragma unroll
            for (int jj = 0; jj < 4; jj++) {
                float s = sacc[i][jj] * 0.03125f;   // C^-0.5 = 1/32
                if (diag && (s0 + tx * 4 + jj) > rg) s = -1e30f;
                sacc[i][jj] = s;
            }
        }

        // online softmax
#pragma unroll
        for (int i = 0; i < 2; i++) {
            float mx = fmaxf(fmaxf(sacc[i][0], sacc[i][1]),
                             fmaxf(sacc[i][2], sacc[i][3]));
#pragma unroll
            for (int off = 8; off; off >>= 1)
                mx = fmaxf(mx, __shfl_xor_sync(0xffffffffu, mx, off));
            float newm = fmaxf(m_i[i], mx);
            float corr = __expf(m_i[i] - newm);
            float psum = 0.f;
#pragma unroll
            for (int jj = 0; jj < 4; jj++) {
                float p = __expf(sacc[i][jj] - newm);
                sacc[i][jj] = p;
                psum += p;
            }
#pragma unroll
            for (int off = 8; off; off >>= 1)
                psum += __shfl_xor_sync(0xffffffffu, psum, off);
            l_i[i] = l_i[i] * corr + psum;
            m_i[i] = newm;
#pragma unroll
            for (int jj = 0; jj < 4; jj++) o[i][jj] *= corr;
        }

        // P -> smem (reuse Ks)
#pragma unroll
        for (int i = 0; i < 2; i++) {
            int r = ty * 2 + i;
            Ks[r][tx * 4 + 0] = sacc[i][0];
            Ks[r][tx * 4 + 1] = sacc[i][1];
            Ks[r][tx * 4 + 2] = sacc[i][2];
            Ks[r][tx * 4 + 3] = sacc[i][3];
        }
        __syncthreads();

        // O += P @ V
#pragma unroll 8
        for (int s = 0; s < 64; s++) {
            float p0 = Ks[ty * 2][s], p1 = Ks[ty * 2 + 1][s];
            float4 vv = *(const float4*)&Vs[s][tx * 4];
            o[0][0] = fmaf(p0, vv.x, o[0][0]);
            o[0][1] = fmaf(p0, vv.y, o[0][1]);
            o[0][2] = fmaf(p0, vv.z, o[0][2]);
            o[0][3] = fmaf(p0, vv.w, o[0][3]);
            o[1][0] = fmaf(p1, vv.x, o[1][0]);
            o[1][1] = fmaf(p1, vv.y, o[1][1]);
            o[1][2] = fmaf(p1, vv.z, o[1][2]);
            o[1][3] = fmaf(p1, vv.w, o[1][3]);
        }
        __syncthreads();
    }

    // normalize + write [B,T,C] (concat heads)
    int b = bh >> 4, h = bh & 15;
#pragma unroll
    for (int i = 0; i < 2; i++) {
        float inv = 1.f / l_i[i];
        int t = m0 + ty * 2 + i;
        float4 ov;
        ov.x = o[i][0] * inv; ov.y = o[i][1] * inv;
        ov.z = o[i][2] * inv; ov.w = o[i][3] * inv;
        *(float4*)(Out + (size_t)(b * TSEQ + t) * CDIM + h * HSZ + tx * 4) = ov;
    }
}

// ---------------------------------------------------------------------------
extern "C" void kernel_launch(void* const* d_in, const int* in_sizes, int n_in,
                              void* d_out, int out_size) {
    const float* x    = (const float*)d_in[0];
    const float* ln1g = (const float*)d_in[1];
    const float* ln1b = (const float*)d_in[2];
    const float* ln2g = (const float*)d_in[3];
    const float* ln2b = (const float*)d_in[4];
    const float* Wq   = (const float*)d_in[5];
    const float* bq   = (const float*)d_in[6];
    const float* Wk   = (const float*)d_in[7];
    const float* bk   = (const float*)d_in[8];
    const float* Wv   = (const float*)d_in[9];
    const float* bv   = (const float*)d_in[10];
    const float* Wo   = (const float*)d_in[11];
    const float* bo   = (const float*)d_in[12];
    const float* W1   = (const float*)d_in[13];
    const float* b1   = (const float*)d_in[14];
    const float* W2   = (const float*)d_in[15];
    const float* b2   = (const float*)d_in[16];
    float* out = (float*)d_out;

    float *h1, *q, *k, *v, *att, *x2, *h2, *ff;
    cudaGetSymbolAddress((void**)&h1,  g_h1);
    cudaGetSymbolAddress((void**)&q,   g_q);
    cudaGetSymbolAddress((void**)&k,   g_k);
    cudaGetSymbolAddress((void**)&v,   g_v);
    cudaGetSymbolAddress((void**)&att, g_att);
    cudaGetSymbolAddress((void**)&x2,  g_x2);
    cudaGetSymbolAddress((void**)&h2,  g_h2);
    cudaGetSymbolAddress((void**)&ff,  g_ff);

    dim3 lnGrid(BATCH, CDIM / 32), lnBlk(32, 16);
    dim3 gBlk(256);
    dim3 gSq(CDIM / 128, BT / 128);     // 1024-wide GEMMs
    dim3 gF1(FDIM / 128, BT / 128);     // FFN1

    // 1) LN1 over time
    ln_time_kernel<<<lnGrid, lnBlk>>>(x, ln1g, ln1b, h1);
    // 2) QKV projections -> [B,H,T,HS]
    gemm_kernel<0><<<gSq, gBlk>>>(h1, Wq, bq, nullptr, q,  BT, CDIM, CDIM);
    gemm_kernel<0><<<gSq, gBlk>>>(h1, Wk, bk, nullptr, k,  BT, CDIM, CDIM);
    gemm_kernel<0><<<gSq, gBlk>>>(h1, Wv, bv, nullptr, v,  BT, CDIM, CDIM);
    // 3) causal attention -> [B,T,C]
    attn_kernel<<<dim3(TSEQ / 32, BATCH * NHEAD), 256>>>(q, k, v, att);
    // 4) output projection + residual
    gemm_kernel<1><<<gSq, gBlk>>>(att, Wo, bo, x, x2, BT, CDIM, CDIM);
    // 5) LN2 over time
    ln_time_kernel<<<lnGrid, lnBlk>>>(x2, ln2g, ln2b, h2);
    // 6) FFN1 + ReLU
    gemm_kernel<2><<<gF1, gBlk>>>(h2, W1, b1, nullptr, ff, BT, FDIM, CDIM);
    // 7) FFN2 + residual -> out
    gemm_kernel<3><<<gSq, gBlk>>>(ff, W2, b2, x2, out, BT, CDIM, FDIM);
}

// round 3
// speedup vs baseline: 2.3387x; 2.3387x over previous
#include <cuda_runtime.h>
#include <cstdint>

#define BATCH 4
#define TSEQ  2048
#define CDIM  1024
#define NHEAD 16
#define HSZ   64
#define FDIM  4096
#define BT    (BATCH * TSEQ)   // 8192
#define LN_EPS 1e-5f

// ---------------- scratch (device globals: allocation-free) ----------------
__device__ float g_h1[BT * CDIM];
__device__ float g_q [BT * CDIM];    // [B,H,T,HS]
__device__ float g_k [BT * CDIM];
__device__ float g_v [BT * CDIM];
__device__ float g_att[BT * CDIM];
__device__ float g_x2[BT * CDIM];
__device__ float g_h2[BT * CDIM];
__device__ float g_ff[BT * FDIM];

// ---------------- helpers ----------------
__device__ __forceinline__ uint32_t f2tf32(float f) {
    uint32_t o;
    asm("cvt.rna.tf32.f32 %0, %1;" : "=r"(o) : "f"(f));
    return o;
}

__device__ __forceinline__ void mma16n8k8(float c[4], const uint32_t a[4], const uint32_t b[2]) {
    asm volatile(
        "mma.sync.aligned.m16n8k8.row.col.f32.tf32.tf32.f32 "
        "{%0,%1,%2,%3}, {%4,%5,%6,%7}, {%8,%9}, {%0,%1,%2,%3};"
        : "+f"(c[0]), "+f"(c[1]), "+f"(c[2]), "+f"(c[3])
        : "r"(a[0]), "r"(a[1]), "r"(a[2]), "r"(a[3]), "r"(b[0]), "r"(b[1]));
}

// ---------------- LayerNorm over TIME axis (axis=1), ddof=1 ----------------
__global__ void ln_time_kernel(const float* __restrict__ x,
                               const float* __restrict__ gamma,
                               const float* __restrict__ beta,
                               float* __restrict__ out) {
    int b  = blockIdx.x;
    int c  = blockIdx.y * 32 + threadIdx.x;
    int ty = threadIdx.y;
    const float* xp = x + (size_t)b * TSEQ * CDIM + c;

    float s = 0.f, s2 = 0.f;
    for (int t = ty; t < TSEQ; t += 16) {
        float v = xp[(size_t)t * CDIM];
        s += v; s2 += v * v;
    }
    __shared__ float sh1[16][33];
    __shared__ float sh2[16][33];
    sh1[ty][threadIdx.x] = s;
    sh2[ty][threadIdx.x] = s2;
    __syncthreads();
    for (int off = 8; off; off >>= 1) {
        if (ty < off) {
            sh1[ty][threadIdx.x] += sh1[ty + off][threadIdx.x];
            sh2[ty][threadIdx.x] += sh2[ty + off][threadIdx.x];
        }
        __syncthreads();
    }
    float mean = sh1[0][threadIdx.x] * (1.f / TSEQ);
    float var  = (sh2[0][threadIdx.x] - (float)TSEQ * mean * mean) * (1.f / (TSEQ - 1));
    float inv  = rsqrtf(var + LN_EPS);
    float gg = gamma[c], bb = beta[c];

    float* op = out + (size_t)b * TSEQ * CDIM + c;
    for (int t = ty; t < TSEQ; t += 16) {
        op[(size_t)t * CDIM] = (xp[(size_t)t * CDIM] - mean) * inv * gg + bb;
    }
}

// ---------------- tf32 tensor-core GEMM: 128x128x16, 256 thr, 8 warps -----
// Warp grid 2(m) x 4(n): warp tile 64x32. mma m16n8k8, 4 mtiles x 4 ntiles.
// MODE 0: B = [H, C, HS] stacked weights; out -> [B,H,T,HS] + bias
// MODE 1/3: out = A@B + bias + res ; MODE 2: out = relu(A@B + bias)
template <int MODE>
__global__ __launch_bounds__(256)
void gemm_tc(const float* __restrict__ A, const float* __restrict__ Bw,
             const float* __restrict__ bias, const float* __restrict__ res,
             float* __restrict__ out, int M, int N, int K) {
    __shared__ float As[128][20];   // [m][k], pad to 20 (80B rows, 16B-aligned)
    __shared__ float Bs[16][132];   // [k][n], pad to 132

    int tid = threadIdx.x;
    int warp = tid >> 5, lane = tid & 31;
    int grp = lane >> 2, qp = lane & 3;
    int wm = (warp >> 2) * 64;      // warp m-offset in tile
    int wn = (warp & 3) * 32;       // warp n-offset in tile
    int m0 = blockIdx.y * 128, n0 = blockIdx.x * 128;

    // ---- gmem load mapping (2 float4 of A, 2 float4 of B per thread) ----
    int ra[2], ca[2], rb[2];
    const float* aptr[2];
    const float* bptr[2];
    size_t bstride;
#pragma unroll
    for (int e = 0; e < 2; e++) {
        int i = tid + e * 256;
        ra[e] = i >> 2; ca[e] = (i & 3) * 4;
        aptr[e] = A + (size_t)(m0 + ra[e]) * K + ca[e];
        int ib = tid + e * 256;
        rb[e] = ib >> 5;
        int n = n0 + (ib & 31) * 4;
        if (MODE == 0) {
            bptr[e] = Bw + (size_t)(n >> 6) * K * 64 + (n & 63);
        } else {
            bptr[e] = Bw + n;
        }
    }
    bstride = (MODE == 0) ? 64 : (size_t)N;

    float acc[4][4][4];
#pragma unroll
    for (int mt = 0; mt < 4; mt++)
#pragma unroll
        for (int nt = 0; nt < 4; nt++)
#pragma unroll
            for (int r = 0; r < 4; r++) acc[mt][nt][r] = 0.f;

    float4 aReg[2], bReg[2];
    // prologue load k0 = 0
#pragma unroll
    for (int e = 0; e < 2; e++) {
        aReg[e] = *(const float4*)(aptr[e]);
        bReg[e] = *(const float4*)(bptr[e] + (size_t)rb[e] * bstride);
    }
    // store to smem (tf32-converted)
#pragma unroll
    for (int e = 0; e < 2; e++) {
        uint32_t* as = (uint32_t*)&As[ra[e]][ca[e]];
        as[0] = f2tf32(aReg[e].x); as[1] = f2tf32(aReg[e].y);
        as[2] = f2tf32(aReg[e].z); as[3] = f2tf32(aReg[e].w);
        int i = tid + e * 256;
        uint32_t* bs = (uint32_t*)&Bs[rb[e]][(i & 31) * 4];
        bs[0] = f2tf32(bReg[e].x); bs[1] = f2tf32(bReg[e].y);
        bs[2] = f2tf32(bReg[e].z); bs[3] = f2tf32(bReg[e].w);
    }
    __syncthreads();

    for (int k0 = 0; k0 < K; k0 += 16) {
        bool more = (k0 + 16) < K;
        if (more) {
#pragma unroll
            for (int e = 0; e < 2; e++) {
                aReg[e] = *(const float4*)(aptr[e] + k0 + 16);
                bReg[e] = *(const float4*)(bptr[e] + (size_t)(k0 + 16 + rb[e]) * bstride);
            }
        }
        // ---- compute over 2 k-steps of 8 ----
#pragma unroll
        for (int kk = 0; kk < 2; kk++) {
            uint32_t af[4][4], bf[4][2];
            int kcol = kk * 8 + qp;
#pragma unroll
            for (int mt = 0; mt < 4; mt++) {
                int r = wm + mt * 16 + grp;
                af[mt][0] = __float_as_uint(As[r][kcol]);
                af[mt][1] = __float_as_uint(As[r + 8][kcol]);
                af[mt][2] = __float_as_uint(As[r][kcol + 4]);
                af[mt][3] = __float_as_uint(As[r + 8][kcol + 4]);
            }
#pragma unroll
            for (int nt = 0; nt < 4; nt++) {
                int c = wn + nt * 8 + grp;
                bf[nt][0] = __float_as_uint(Bs[kcol][c]);
                bf[nt][1] = __float_as_uint(Bs[kcol + 4][c]);
            }
#pragma unroll
            for (int mt = 0; mt < 4; mt++)
#pragma unroll
                for (int nt = 0; nt < 4; nt++)
                    mma16n8k8(acc[mt][nt], af[mt], bf[nt]);
        }
        __syncthreads();
        if (more) {
#pragma unroll
            for (int e = 0; e < 2; e++) {
                uint32_t* as = (uint32_t*)&As[ra[e]][ca[e]];
                as[0] = f2tf32(aReg[e].x); as[1] = f2tf32(aReg[e].y);
                as[2] = f2tf32(aReg[e].z); as[3] = f2tf32(aReg[e].w);
                int i = tid + e * 256;
                uint32_t* bs = (uint32_t*)&Bs[rb[e]][(i & 31) * 4];
                bs[0] = f2tf32(bReg[e].x); bs[1] = f2tf32(bReg[e].y);
                bs[2] = f2tf32(bReg[e].z); bs[3] = f2tf32(bReg[e].w);
            }
            __syncthreads();
        }
    }

    // ---- epilogue ----
#pragma unroll
    for (int mt = 0; mt < 4; mt++) {
#pragma unroll
        for (int nt = 0; nt < 4; nt++) {
            int c = n0 + wn + nt * 8 + qp * 2;
            float bi0 = bias[c], bi1 = bias[c + 1];
#pragma unroll
            for (int half = 0; half < 2; half++) {
                int r = m0 + wm + mt * 16 + grp + half * 8;
                float v0 = acc[mt][nt][half * 2 + 0] + bi0;
                float v1 = acc[mt][nt][half * 2 + 1] + bi1;
                if (MODE == 0) {
                    int b = r >> 11, t = r & 2047;
                    int h = c >> 6, d = c & 63;
                    float2* p = (float2*)&((float*)out)[((size_t)(b * NHEAD + h) * TSEQ + t) * HSZ + d];
                    *p = make_float2(v0, v1);
                } else if (MODE == 2) {
                    float2* p = (float2*)&out[(size_t)r * N + c];
                    *p = make_float2(fmaxf(v0, 0.f), fmaxf(v1, 0.f));
                } else {
                    const float2 rr = *(const float2*)&res[(size_t)r * N + c];
                    float2* p = (float2*)&out[(size_t)r * N + c];
                    *p = make_float2(v0 + rr.x, v1 + rr.y);
                }
            }
        }
    }
}

// ---------------- causal flash attention, BM=64, BN=64, HS=64 --------------
// 256 threads. ty=tid>>4 owns rows ty*4..+3; tx=tid&15 owns cols tx*4..+3.
// Row reductions via shfl within 16-lane halves. Dynamic smem (49.4 KB).
#define ATTN_SMEM ((64 * 64 + 64 * 65 + 64 * 64) * 4)
__global__ __launch_bounds__(256)
void attn_kernel(const float* __restrict__ Q, const float* __restrict__ Kg,
                 const float* __restrict__ V, float* __restrict__ Out) {
    extern __shared__ float sm[];
    float* Qs = sm;               // [64][64]
    float* Ks = sm + 64 * 64;     // [64][65]  (reused for P)
    float* Vs = Ks + 64 * 65;     // [64][64]
#define QS(r, c) Qs[(r) * 64 + (c)]
#define KS(r, c) Ks[(r) * 65 + (c)]
#define VS(r, c) Vs[(r) * 64 + (c)]

    int bh = blockIdx.y;
    int m0 = blockIdx.x * 64;
    int tid = threadIdx.x;
    int tx = tid & 15, ty = tid >> 4;

    const float* Qb = Q  + (size_t)bh * TSEQ * HSZ;
    const float* Kb = Kg + (size_t)bh * TSEQ * HSZ;
    const float* Vb = V  + (size_t)bh * TSEQ * HSZ;

    for (int i = tid; i < 64 * 16; i += 256) {
        int r = i >> 4, c4 = (i & 15) << 2;
        *(float4*)&QS(r, c4) = *(const float4*)(Qb + (size_t)(m0 + r) * HSZ + c4);
    }

    float m_i[4] = {-1e30f, -1e30f, -1e30f, -1e30f};
    float l_i[4] = {0.f, 0.f, 0.f, 0.f};
    float o[4][4];
#pragma unroll
    for (int i = 0; i < 4; i++)
#pragma unroll
        for (int j = 0; j < 4; j++) o[i][j] = 0.f;

    int jmax = m0 >> 6;
    __syncthreads();

    for (int j = 0; j <= jmax; j++) {
        int s0 = j << 6;
        for (int i = tid; i < 64 * 16; i += 256) {
            int r = i >> 4, c4 = (i & 15) << 2;
            float4 kv = *(const float4*)(Kb + (size_t)(s0 + r) * HSZ + c4);
            KS(r, c4) = kv.x; KS(r, c4 + 1) = kv.y;
            KS(r, c4 + 2) = kv.z; KS(r, c4 + 3) = kv.w;
            *(float4*)&VS(r, c4) = *(const float4*)(Vb + (size_t)(s0 + r) * HSZ + c4);
        }
        __syncthreads();

        // S = Q @ K^T (4x4 per thread)
        float sacc[4][4];
#pragma unroll
        for (int i = 0; i < 4; i++)
#pragma unroll
            for (int jj = 0; jj < 4; jj++) sacc[i][jj] = 0.f;

#pragma unroll 8
        for (int k = 0; k < 64; k++) {
            float qv[4], kv[4];
#pragma unroll
            for (int i = 0; i < 4; i++) qv[i] = QS(ty * 4 + i, k);
#pragma unroll
            for (int jj = 0; jj < 4; jj++) kv[jj] = KS(tx * 4 + jj, k);
#pragma unroll
            for (int i = 0; i < 4; i++)
#pragma unroll
                for (int jj = 0; jj < 4; jj++)
                    sacc[i][jj] = fmaf(qv[i], kv[jj], sacc[i][jj]);
        }
        __syncthreads();  // done reading Ks before P overwrites it

        bool diag = (j == jmax);
#pragma unroll
        for (int i = 0; i < 4; i++) {
            int rg = m0 + ty * 4 + i;
#pragma unroll
            for (int jj = 0; jj < 4; jj++) {
                float s = sacc[i][jj] * 0.03125f;   // C^-0.5 = 1/32
                if (diag && (s0 + tx * 4 + jj) > rg) s = -1e30f;
                sacc[i][jj] = s;
            }
        }

        // online softmax
#pragma unroll
        for (int i = 0; i < 4; i++) {
            float mx = fmaxf(fmaxf(sacc[i][0], sacc[i][1]),
                             fmaxf(sacc[i][2], sacc[i][3]));
#pragma unroll
            for (int off = 8; off; off >>= 1)
                mx = fmaxf(mx, __shfl_xor_sync(0xffffffffu, mx, off));
            float newm = fmaxf(m_i[i], mx);
            float corr = __expf(m_i[i] - newm);
            float psum = 0.f;
#pragma unroll
            for (int jj = 0; jj < 4; jj++) {
                float p = __expf(sacc[i][jj] - newm);
                sacc[i][jj] = p;
                psum += p;
            }
#pragma unroll
            for (int off = 8; off; off >>= 1)
                psum += __shfl_xor_sync(0xffffffffu, psum, off);
            l_i[i] = l_i[i] * corr + psum;
            m_i[i] = newm;
#pragma unroll
            for (int jj = 0; jj < 4; jj++) o[i][jj] *= corr;
        }

        // P -> smem (reuse Ks)
#pragma unroll
        for (int i = 0; i < 4; i++) {
            KS(ty * 4 + i, tx * 4 + 0) = sacc[i][0];
            KS(ty * 4 + i, tx * 4 + 1) = sacc[i][1];
            KS(ty * 4 + i, tx * 4 + 2) = sacc[i][2];
            KS(ty * 4 + i, tx * 4 + 3) = sacc[i][3];
        }
        __syncthreads();

        // O += P @ V
#pragma unroll 8
        for (int s = 0; s < 64; s++) {
            float pv[4];
#pragma unroll
            for (int i = 0; i < 4; i++) pv[i] = KS(ty * 4 + i, s);
            float4 vv = *(const float4*)&VS(s, tx * 4);
#pragma unroll
            for (int i = 0; i < 4; i++) {
                o[i][0] = fmaf(pv[i], vv.x, o[i][0]);
                o[i][1] = fmaf(pv[i], vv.y, o[i][1]);
                o[i][2] = fmaf(pv[i], vv.z, o[i][2]);
                o[i][3] = fmaf(pv[i], vv.w, o[i][3]);
            }
        }
        __syncthreads();
    }

    int b = bh >> 4, h = bh & 15;
#pragma unroll
    for (int i = 0; i < 4; i++) {
        float inv = 1.f / l_i[i];
        int t = m0 + ty * 4 + i;
        float4 ov;
        ov.x = o[i][0] * inv; ov.y = o[i][1] * inv;
        ov.z = o[i][2] * inv; ov.w = o[i][3] * inv;
        *(float4*)(Out + (size_t)(b * TSEQ + t) * CDIM + h * HSZ + tx * 4) = ov;
    }
}

// ---------------------------------------------------------------------------
extern "C" void kernel_launch(void* const* d_in, const int* in_sizes, int n_in,
                              void* d_out, int out_size) {
    const float* x    = (const float*)d_in[0];
    const float* ln1g = (const float*)d_in[1];
    const float* ln1b = (const float*)d_in[2];
    const float* ln2g = (const float*)d_in[3];
    const float* ln2b = (const float*)d_in[4];
    const float* Wq   = (const float*)d_in[5];
    const float* bq   = (const float*)d_in[6];
    const float* Wk   = (const float*)d_in[7];
    const float* bk   = (const float*)d_in[8];
    const float* Wv   = (const float*)d_in[9];
    const float* bv   = (const float*)d_in[10];
    const float* Wo   = (const float*)d_in[11];
    const float* bo   = (const float*)d_in[12];
    const float* W1   = (const float*)d_in[13];
    const float* b1   = (const float*)d_in[14];
    const float* W2   = (const float*)d_in[15];
    const float* b2   = (const float*)d_in[16];
    float* out = (float*)d_out;

    float *h1, *q, *k, *v, *att, *x2, *h2, *ff;
    cudaGetSymbolAddress((void**)&h1,  g_h1);
    cudaGetSymbolAddress((void**)&q,   g_q);
    cudaGetSymbolAddress((void**)&k,   g_k);
    cudaGetSymbolAddress((void**)&v,   g_v);
    cudaGetSymbolAddress((void**)&att, g_att);
    cudaGetSymbolAddress((void**)&x2,  g_x2);
    cudaGetSymbolAddress((void**)&h2,  g_h2);
    cudaGetSymbolAddress((void**)&ff,  g_ff);

    cudaFuncSetAttribute(attn_kernel, cudaFuncAttributeMaxDynamicSharedMemorySize, ATTN_SMEM);

    dim3 lnGrid(BATCH, CDIM / 32), lnBlk(32, 16);
    dim3 gBlk(256);
    dim3 gSq(CDIM / 128, BT / 128);
    dim3 gF1(FDIM / 128, BT / 128);

    ln_time_kernel<<<lnGrid, lnBlk>>>(x, ln1g, ln1b, h1);
    gemm_tc<0><<<gSq, gBlk>>>(h1, Wq, bq, nullptr, q,  BT, CDIM, CDIM);
    gemm_tc<0><<<gSq, gBlk>>>(h1, Wk, bk, nullptr, k,  BT, CDIM, CDIM);
    gemm_tc<0><<<gSq, gBlk>>>(h1, Wv, bv, nullptr, v,  BT, CDIM, CDIM);
    attn_kernel<<<dim3(TSEQ / 64, BATCH * NHEAD), 256, ATTN_SMEM>>>(q, k, v, att);
    gemm_tc<1><<<gSq, gBlk>>>(att, Wo, bo, x, x2, BT, CDIM, CDIM);
    ln_time_kernel<<<lnGrid, lnBlk>>>(x2, ln2g, ln2b, h2);
    gemm_tc<2><<<gF1, gBlk>>>(h2, W1, b1, nullptr, ff, BT, FDIM, CDIM);
    gemm_tc<3><<<gSq, gBlk>>>(ff, W2, b2, x2, out, BT, CDIM, FDIM);
}